// round 1
// baseline (speedup 1.0000x reference)
#include <cuda_runtime.h>

// Problem constants (match reference)
#define NGRID 48
#define N3 (NGRID * NGRID * NGRID)
#define NATOMS_MAX 1024
#define TILE_X 4
#define TILE_Y 4
#define TILES_X (NGRID / TILE_X)   // 12
#define TILES_Y (NGRID / TILE_Y)   // 12
#define NBLOCKS (TILES_X * TILES_Y) // 144
#define NTHREADS 256

// r^2 computed exactly as the reference: float32((1.5*1.52)**2) with the
// intermediate product in double precision (python float semantics).
__device__ __forceinline__ float ref_r2() {
    const double r = 1.5 * 1.52;
    return (float)(r * r);
}

__global__ __launch_bounds__(NTHREADS)
void wat_mask_kernel(const float* __restrict__ vecs, int n_atoms,
                     float* __restrict__ out) {
    __shared__ float sx[NATOMS_MAX];
    __shared__ float sy[NATOMS_MAX];
    __shared__ float sz[NATOMS_MAX];
    __shared__ int s_cnt;

    const float GRIDF = 0.5f;
    const float R2 = ref_r2();           // ~5.1984
    const float RMARG = 2.2801f;         // > sqrt(R2), conservative cull margin

    const int bx = blockIdx.x % TILES_X;
    const int by = blockIdx.x / TILES_X;
    const int x0 = bx * TILE_X;
    const int y0 = by * TILE_Y;

    // Tile AABB (in coordinate space), expanded by radius for culling.
    const float xmin = GRIDF * (float)x0 - RMARG;
    const float xmax = GRIDF * (float)(x0 + TILE_X - 1) + RMARG;
    const float ymin = GRIDF * (float)y0 - RMARG;
    const float ymax = GRIDF * (float)(y0 + TILE_Y - 1) + RMARG;
    // z spans the full axis for this tile -> no z culling.

    if (threadIdx.x == 0) s_cnt = 0;
    __syncthreads();

    // Phase 1: cull atoms against the expanded tile AABB into shared memory.
    for (int i = threadIdx.x; i < n_atoms; i += NTHREADS) {
        const float ax = vecs[3 * i + 0];
        const float ay = vecs[3 * i + 1];
        const float az = vecs[3 * i + 2];
        if (ax >= xmin && ax <= xmax && ay >= ymin && ay <= ymax) {
            const int p = atomicAdd(&s_cnt, 1);
            sx[p] = ax; sy[p] = ay; sz[p] = az;
        }
    }
    __syncthreads();
    const int cnt = s_cnt;

    // Phase 2: each thread any-tests its voxels against the culled atom list.
    // 4*4*48 = 768 voxels per tile, 256 threads -> 3 voxels/thread.
    // v % NGRID = z (contiguous) -> coalesced stores along z.
    for (int v = threadIdx.x; v < TILE_X * TILE_Y * NGRID; v += NTHREADS) {
        const int gz = v % NGRID;
        const int gy = y0 + (v / NGRID) % TILE_Y;
        const int gx = x0 + v / (NGRID * TILE_Y);

        // Voxel coordinate 0.5*i is exact in fp32 (matches GRID*arange).
        const float px = GRIDF * (float)gx;
        const float py = GRIDF * (float)gy;
        const float pz = GRIDF * (float)gz;

        bool found = false;
        for (int j = 0; j < cnt && !found; ++j) {
            const float dx = sx[j] - px;
            const float dy = sy[j] - py;
            const float dz = sz[j] - pz;
            // Exact reference rounding: (dx^2 + dy^2) + dz^2, no FMA fusion.
            const float d2 = __fadd_rn(__fadd_rn(__fmul_rn(dx, dx),
                                                 __fmul_rn(dy, dy)),
                                       __fmul_rn(dz, dz));
            found = (d2 < R2);
        }

        const int idx = (gx * NGRID + gy) * NGRID + gz;
        out[idx]      = found ? 1.0f  : 0.0f;   // channel 0
        out[idx + N3] = found ? 25.0f : 1.0f;   // channel 1
    }
}

extern "C" void kernel_launch(void* const* d_in, const int* in_sizes, int n_in,
                              void* d_out, int out_size) {
    const float* vecs = (const float*)d_in[0];
    const int n_atoms = in_sizes[0] / 3;
    float* out = (float*)d_out;
    wat_mask_kernel<<<NBLOCKS, NTHREADS>>>(vecs, n_atoms, out);
}

// round 2
// speedup vs baseline: 1.8423x; 1.8423x over previous
#include <cuda_runtime.h>

#define NGRID 48
#define N3 (NGRID * NGRID * NGRID)
#define NATOMS_MAX 1024
#define TILE 4
#define TILES_X (NGRID / TILE)        // 12
#define NBLOCKS (TILES_X * TILES_X)   // 144
#define NTHREADS 256

// r^2 exactly as the reference: float32((1.5*1.52)**2), product in double.
__device__ __forceinline__ float ref_r2() {
    const double r = 1.5 * 1.52;
    return (float)(r * r);
}

__global__ __launch_bounds__(NTHREADS)
void wat_mask_kernel(const float* __restrict__ vecs, int n_atoms,
                     float* __restrict__ out) {
    __shared__ float sx[NATOMS_MAX];
    __shared__ float sy[NATOMS_MAX];
    __shared__ float sz[NATOMS_MAX];
    __shared__ unsigned long long smask[TILE * TILE];
    __shared__ int s_cnt;

    const float R2 = ref_r2();          // ~5.1984
    const float RM = 2.2802f;           // > sqrt(R2): conservative cull margin

    const int bx = blockIdx.x % TILES_X;
    const int by = blockIdx.x / TILES_X;
    const int x0 = bx * TILE;
    const int y0 = by * TILE;

    const float xmin = 0.5f * (float)x0 - RM;
    const float xmax = 0.5f * (float)(x0 + TILE - 1) + RM;
    const float ymin = 0.5f * (float)y0 - RM;
    const float ymax = 0.5f * (float)(y0 + TILE - 1) + RM;

    if (threadIdx.x == 0) s_cnt = 0;
    __syncthreads();

    // Phase 1: cull atoms against expanded tile AABB into shared memory.
    for (int i = threadIdx.x; i < n_atoms; i += NTHREADS) {
        const float ax = vecs[3 * i + 0];
        const float ay = vecs[3 * i + 1];
        const float az = vecs[3 * i + 2];
        if (ax >= xmin && ax <= xmax && ay >= ymin && ay <= ymax) {
            const int p = atomicAdd(&s_cnt, 1);
            sx[p] = ax; sy[p] = ay; sz[p] = az;
        }
    }
    __syncthreads();
    const int cnt = s_cnt;

    // Phase 2: warp-per-column. For each culled atom, the passing z-set is a
    // contiguous interval (RN-monotone), found by sqrt estimate + exact
    // boundary walk-in using the reference-rounded test. Lanes stride atoms;
    // masks are OR-reduced across the warp.
    const int wid  = threadIdx.x >> 5;   // 8 warps
    const int lane = threadIdx.x & 31;

    for (int c = wid; c < TILE * TILE; c += NTHREADS / 32) {
        const int cx = c >> 2;           // col index encodes (cx, cy): cy fastest
        const int cy = c & 3;
        const float px = 0.5f * (float)(x0 + cx);  // exact in fp32
        const float py = 0.5f * (float)(y0 + cy);

        unsigned long long mask = 0ull;
        for (int j = lane; j < cnt; j += 32) {
            const float dx  = __fsub_rn(sx[j], px);
            const float dy  = __fsub_rn(sy[j], py);
            const float sxy = __fadd_rn(__fmul_rn(dx, dx), __fmul_rn(dy, dy));
            if (sxy >= R2) continue;     // rigorous: RN(sxy+dz^2) >= sxy >= R2

            const float az  = sz[j];
            const float rad = sqrtf(__fsub_rn(R2, sxy));
            int zl = (int)ceilf((az - rad) * 2.0f) - 1;
            int zh = (int)floorf((az + rad) * 2.0f) + 1;
            zl = max(zl, 0);
            zh = min(zh, NGRID - 1);

            // Exact walk-in at both ends (reference-rounded comparison).
            while (zl <= zh) {
                const float dz = __fsub_rn(az, 0.5f * (float)zl);
                if (__fadd_rn(sxy, __fmul_rn(dz, dz)) < R2) break;
                ++zl;
            }
            while (zh >= zl) {
                const float dz = __fsub_rn(az, 0.5f * (float)zh);
                if (__fadd_rn(sxy, __fmul_rn(dz, dz)) < R2) break;
                --zh;
            }
            if (zl <= zh) {
                const int len = zh - zl + 1;
                const unsigned long long run =
                    (len >= 64) ? ~0ull : ((1ull << len) - 1ull);
                mask |= run << zl;
            }
        }
        #pragma unroll
        for (int off = 16; off; off >>= 1)
            mask |= __shfl_xor_sync(0xffffffffu, mask, off);
        if (lane == 0) smask[c] = mask;
    }
    __syncthreads();

    // Phase 3: coalesced write of both channels from the column masks.
    #pragma unroll
    for (int v = threadIdx.x; v < TILE * TILE * NGRID; v += NTHREADS) {
        const int z   = v % NGRID;
        const int col = v / NGRID;                 // cy fastest -> addresses ascend
        const bool on = (smask[col] >> z) & 1ull;
        const int gx = x0 + (col >> 2);
        const int gy = y0 + (col & 3);
        const int idx = (gx * NGRID + gy) * NGRID + z;
        out[idx]      = on ? 1.0f  : 0.0f;   // channel 0
        out[idx + N3] = on ? 25.0f : 1.0f;   // channel 1
    }
}

extern "C" void kernel_launch(void* const* d_in, const int* in_sizes, int n_in,
                              void* d_out, int out_size) {
    const float* vecs = (const float*)d_in[0];
    const int n_atoms = in_sizes[0] / 3;
    float* out = (float*)d_out;
    wat_mask_kernel<<<NBLOCKS, NTHREADS>>>(vecs, n_atoms, out);
}

// round 3
// speedup vs baseline: 2.4712x; 1.3413x over previous
#include <cuda_runtime.h>

#define NGRID 48
#define N3 (NGRID * NGRID * NGRID)
#define NATOMS_MAX 1024
#define TILE 4
#define TILES_X (NGRID / TILE)        // 12
#define NBLOCKS (TILES_X * TILES_X)   // 144
#define NTHREADS 512

// r^2 exactly as the reference: float32((1.5*1.52)**2), product in double.
__device__ __forceinline__ float ref_r2() {
    const double r = 1.5 * 1.52;
    return (float)(r * r);
}

__global__ __launch_bounds__(NTHREADS)
void wat_mask_kernel(const float* __restrict__ vecs, int n_atoms,
                     float* __restrict__ out) {
    __shared__ float4 satom[NATOMS_MAX];              // packed (x,y,z,_)
    __shared__ unsigned long long smask[TILE * TILE]; // per-column 48-bit mask
    __shared__ int s_cnt;

    const float R2 = ref_r2();          // ~5.1984
    const float RM = 2.2802f;           // > sqrt(R2): conservative cull margin

    const int bx = blockIdx.x % TILES_X;
    const int by = blockIdx.x / TILES_X;
    const int x0 = bx * TILE;
    const int y0 = by * TILE;

    const float xmin = 0.5f * (float)x0 - RM;
    const float xmax = 0.5f * (float)(x0 + TILE - 1) + RM;
    const float ymin = 0.5f * (float)y0 - RM;
    const float ymax = 0.5f * (float)(y0 + TILE - 1) + RM;

    const int tid  = threadIdx.x;
    const int wid  = tid >> 5;          // 16 warps
    const int lane = tid & 31;

    if (tid == 0) s_cnt = 0;
    __syncthreads();

    // Phase 1: cull atoms vs expanded tile AABB, warp-aggregated compaction.
    for (int base = 0; base < n_atoms; base += NTHREADS) {
        const int i = base + tid;
        const bool in = (i < n_atoms);
        float ax = 0.f, ay = 0.f, az = 0.f;
        if (in) {
            ax = vecs[3 * i + 0];
            ay = vecs[3 * i + 1];
            az = vecs[3 * i + 2];
        }
        const bool match = in && ax >= xmin && ax <= xmax
                              && ay >= ymin && ay <= ymax;
        const unsigned m = __ballot_sync(0xffffffffu, match);
        int wbase = 0;
        if (lane == 0 && m) wbase = atomicAdd(&s_cnt, __popc(m));
        wbase = __shfl_sync(0xffffffffu, wbase, 0);
        if (match) {
            const int p = wbase + __popc(m & ((1u << lane) - 1u));
            satom[p] = make_float4(ax, ay, az, 0.f);
        }
    }
    __syncthreads();
    const int cnt = s_cnt;

    // Phase 2: one warp per column. Passing z-set per atom is a contiguous
    // interval (RN-monotone); locate via sqrt estimate (+/-1 slack) and
    // exact reference-rounded walk-in at the endpoints. OR masks via REDUX.
    {
        const int c  = wid;              // 16 warps <-> 16 columns
        const int cx = c >> 2;
        const int cy = c & 3;
        const float px = 0.5f * (float)(x0 + cx);   // exact in fp32
        const float py = 0.5f * (float)(y0 + cy);

        unsigned long long mask = 0ull;
        for (int j = lane; j < cnt; j += 32) {
            const float4 a = satom[j];
            const float dx  = __fsub_rn(a.x, px);
            const float dy  = __fsub_rn(a.y, py);
            const float sxy = __fadd_rn(__fmul_rn(dx, dx), __fmul_rn(dy, dy));
            if (sxy >= R2) continue;     // rigorous: RN(sxy+dz^2) >= sxy

            const float az  = a.z;
            const float rad = sqrtf(__fsub_rn(R2, sxy));
            int zl = (int)ceilf((az - rad) * 2.0f) - 1;
            int zh = (int)floorf((az + rad) * 2.0f) + 1;
            zl = max(zl, 0);
            zh = min(zh, NGRID - 1);

            while (zl <= zh) {           // exact walk-in, low end
                const float dz = __fsub_rn(az, 0.5f * (float)zl);
                if (__fadd_rn(sxy, __fmul_rn(dz, dz)) < R2) break;
                ++zl;
            }
            while (zh >= zl) {           // exact walk-in, high end
                const float dz = __fsub_rn(az, 0.5f * (float)zh);
                if (__fadd_rn(sxy, __fmul_rn(dz, dz)) < R2) break;
                --zh;
            }
            if (zl <= zh) {
                const int len = zh - zl + 1;
                const unsigned long long run =
                    (len >= 64) ? ~0ull : ((1ull << len) - 1ull);
                mask |= run << zl;
            }
        }
        const unsigned lo = __reduce_or_sync(0xffffffffu, (unsigned)mask);
        const unsigned hi = __reduce_or_sync(0xffffffffu, (unsigned)(mask >> 32));
        if (lane == 0)
            smask[c] = (unsigned long long)lo |
                       ((unsigned long long)hi << 32);
    }
    __syncthreads();

    // Phase 3: vectorized coalesced writes. 2 ch * 16 cols * 12 float4 = 384.
    if (tid < 2 * TILE * TILE * (NGRID / 4)) {
        const int ch  = tid / (TILE * TILE * (NGRID / 4));
        const int r   = tid % (TILE * TILE * (NGRID / 4));
        const int col = r / (NGRID / 4);
        const int zq  = r % (NGRID / 4);
        const unsigned bits = (unsigned)(smask[col] >> (4 * zq)) & 0xFu;

        const float on  = ch ? 25.0f : 1.0f;
        const float off = ch ? 1.0f  : 0.0f;
        float4 v;
        v.x = (bits & 1u) ? on : off;
        v.y = (bits & 2u) ? on : off;
        v.z = (bits & 4u) ? on : off;
        v.w = (bits & 8u) ? on : off;

        const int gx = x0 + (col >> 2);
        const int gy = y0 + (col & 3);
        const int idx = ch * N3 + (gx * NGRID + gy) * NGRID + 4 * zq;
        *reinterpret_cast<float4*>(out + idx) = v;
    }
}

extern "C" void kernel_launch(void* const* d_in, const int* in_sizes, int n_in,
                              void* d_out, int out_size) {
    const float* vecs = (const float*)d_in[0];
    const int n_atoms = in_sizes[0] / 3;
    float* out = (float*)d_out;
    wat_mask_kernel<<<NBLOCKS, NTHREADS>>>(vecs, n_atoms, out);
}